// round 4
// baseline (speedup 1.0000x reference)
#include <cuda_runtime.h>
#include <math.h>

// Problem constants
#define SS   4096
#define DD   512
#define BB   2
#define KTOP 32
#define NROWS (BB*SS)   // 8192

// GEMM tiling
#define BM 128
#define BN 128
#define BK 16

// ---------------- device scratch (static, no allocation) ----------------
__device__ float g_Hi[NROWS*256];
__device__ float g_Hf[NROWS*256];
__device__ float g_intents[(size_t)NROWS*DD];
__device__ float g_featT[(size_t)BB*DD*SS];
__device__ float g_scores[(size_t)BB*SS*SS];   // 134 MB

__device__ __forceinline__ float gelu_f(float v) {
    // exact GELU (erf form), matches jax.nn.gelu(approximate=False)
    return 0.5f * v * (1.0f + erff(v * 0.7071067811865476f));
}

enum { MODE_GELU = 0, MODE_BIAS = 1, MODE_TRANS = 2 };

// C = act(A[M x K] @ Bw[K x N] + bias), M fixed = NROWS
// MODE_TRANS stores transposed per-batch: featT[b][col][s]
__global__ __launch_bounds__(256) void gemm_mlp(
    const float* __restrict__ A, const float* __restrict__ Bw,
    const float* __restrict__ bias, float* __restrict__ C,
    int N, int K, int mode)
{
    __shared__ __align__(16) float As[BK][BM];
    __shared__ __align__(16) float Bs[BK][BN];

    const int tid = threadIdx.x;
    const int tx = tid & 15, ty = tid >> 4;
    const int rowBase = blockIdx.y * BM;
    const int colBase = blockIdx.x * BN;

    float acc[8][8] = {};

    const int aRow = tid >> 2;          // 0..63
    const int aCol = (tid & 3) << 2;    // 0,4,8,12
    const int bRow = tid >> 5;          // 0..7
    const int bCol = (tid & 31) << 2;   // 0..124

    for (int k0 = 0; k0 < K; k0 += BK) {
        #pragma unroll
        for (int h = 0; h < 2; h++) {
            int r = aRow + h * 64;
            float4 v = *reinterpret_cast<const float4*>(
                A + (size_t)(rowBase + r) * K + k0 + aCol);
            As[aCol+0][r] = v.x; As[aCol+1][r] = v.y;
            As[aCol+2][r] = v.z; As[aCol+3][r] = v.w;
        }
        #pragma unroll
        for (int h = 0; h < 2; h++) {
            int r = bRow + h * 8;
            float4 v = *reinterpret_cast<const float4*>(
                Bw + (size_t)(k0 + r) * N + colBase + bCol);
            *reinterpret_cast<float4*>(&Bs[r][bCol]) = v;
        }
        __syncthreads();

        #pragma unroll
        for (int kk = 0; kk < BK; kk++) {
            float a[8], b[8];
            *reinterpret_cast<float4*>(a)     = *reinterpret_cast<const float4*>(&As[kk][ty*8]);
            *reinterpret_cast<float4*>(a + 4) = *reinterpret_cast<const float4*>(&As[kk][ty*8 + 4]);
            *reinterpret_cast<float4*>(b)     = *reinterpret_cast<const float4*>(&Bs[kk][tx*8]);
            *reinterpret_cast<float4*>(b + 4) = *reinterpret_cast<const float4*>(&Bs[kk][tx*8 + 4]);
            #pragma unroll
            for (int i = 0; i < 8; i++)
                #pragma unroll
                for (int j = 0; j < 8; j++)
                    acc[i][j] = fmaf(a[i], b[j], acc[i][j]);
        }
        __syncthreads();
    }

    #pragma unroll
    for (int i = 0; i < 8; i++) {
        int row = rowBase + ty * 8 + i;
        #pragma unroll
        for (int j = 0; j < 8; j++) {
            int col = colBase + tx * 8 + j;
            float v = acc[i][j] + __ldg(bias + col);
            if (mode == MODE_GELU) v = gelu_f(v);
            if (mode == MODE_TRANS) {
                int bt = row >> 12;
                int s  = row & (SS - 1);
                C[((size_t)bt * N + col) * SS + s] = v;
            } else {
                C[(size_t)row * N + col] = v;
            }
        }
    }
}

// scores[b][i][j] = (intents[b,i,:]·featT[b,:,j]) / sqrt(D) + loc_bias[clip(j-i,-64,63)+64]
// j > i => -inf. Upper-triangle tiles skipped entirely.
__global__ __launch_bounds__(256) void gemm_scores(
    const float* __restrict__ intents, const float* __restrict__ featT,
    const float* __restrict__ loc_bias, float* __restrict__ out)
{
    if (blockIdx.x > blockIdx.y) return;   // strictly above diagonal: never read

    const int bt = blockIdx.z;
    const float* A  = intents + (size_t)bt * SS * DD;
    const float* Bw = featT   + (size_t)bt * DD * SS;

    __shared__ __align__(16) float As[BK][BM];
    __shared__ __align__(16) float Bs[BK][BN];

    const int tid = threadIdx.x;
    const int tx = tid & 15, ty = tid >> 4;
    const int rowBase = blockIdx.y * BM;
    const int colBase = blockIdx.x * BN;

    float acc[8][8] = {};

    const int aRow = tid >> 2;
    const int aCol = (tid & 3) << 2;
    const int bRow = tid >> 5;
    const int bCol = (tid & 31) << 2;

    for (int k0 = 0; k0 < DD; k0 += BK) {
        #pragma unroll
        for (int h = 0; h < 2; h++) {
            int r = aRow + h * 64;
            float4 v = *reinterpret_cast<const float4*>(
                A + (size_t)(rowBase + r) * DD + k0 + aCol);
            As[aCol+0][r] = v.x; As[aCol+1][r] = v.y;
            As[aCol+2][r] = v.z; As[aCol+3][r] = v.w;
        }
        #pragma unroll
        for (int h = 0; h < 2; h++) {
            int r = bRow + h * 8;
            float4 v = *reinterpret_cast<const float4*>(
                Bw + (size_t)(k0 + r) * SS + colBase + bCol);
            *reinterpret_cast<float4*>(&Bs[r][bCol]) = v;
        }
        __syncthreads();

        #pragma unroll
        for (int kk = 0; kk < BK; kk++) {
            float a[8], b[8];
            *reinterpret_cast<float4*>(a)     = *reinterpret_cast<const float4*>(&As[kk][ty*8]);
            *reinterpret_cast<float4*>(a + 4) = *reinterpret_cast<const float4*>(&As[kk][ty*8 + 4]);
            *reinterpret_cast<float4*>(b)     = *reinterpret_cast<const float4*>(&Bs[kk][tx*8]);
            *reinterpret_cast<float4*>(b + 4) = *reinterpret_cast<const float4*>(&Bs[kk][tx*8 + 4]);
            #pragma unroll
            for (int i = 0; i < 8; i++)
                #pragma unroll
                for (int j = 0; j < 8; j++)
                    acc[i][j] = fmaf(a[i], b[j], acc[i][j]);
        }
        __syncthreads();
    }

    const float sqrt_d = sqrtf(512.0f);
    #pragma unroll
    for (int i = 0; i < 8; i++) {
        int row = rowBase + ty * 8 + i;
        #pragma unroll
        for (int j = 0; j < 8; j++) {
            int col = colBase + tx * 8 + j;
            int rel = col - row;
            float v;
            if (rel > 0) {
                v = -INFINITY;
            } else {
                int idx = (rel < -64) ? 0 : (rel + 64);
                v = acc[i][j] / sqrt_d + __ldg(loc_bias + idx);
            }
            out[((size_t)bt * SS + row) * SS + col] = v;
        }
    }
}

// One block per (b,i) row. Exact top-32 with lax.top_k tie semantics
// (lowest index wins ties), then softmax; -inf slots get indices i+1.. and w=0.
__global__ __launch_bounds__(256) void topk_kernel(
    const float* __restrict__ scores, float* __restrict__ out)
{
    __shared__ float sv[SS];
    __shared__ float rv[256];
    __shared__ int   ri[256];
    __shared__ float selv[KTOP];
    __shared__ int   seli[KTOP];

    const int tid = threadIdx.x;
    const int row = blockIdx.x;      // 0..NROWS-1
    const int bt  = row >> 12;
    const int i   = row & (SS - 1);
    const float* srow = scores + ((size_t)bt * SS + i) * SS;
    const int n = i + 1;             // valid candidates (j <= i)

    for (int j = tid; j < n; j += 256) sv[j] = srow[j];
    __syncthreads();

    const int kc = (n < KTOP) ? n : KTOP;
    for (int t = 0; t < kc; t++) {
        float bv = -INFINITY; int bi = n;
        for (int j = tid; j < n; j += 256) {
            float v = sv[j];
            if (v > bv) { bv = v; bi = j; }   // ascending j -> strict > keeps lowest index
        }
        rv[tid] = bv; ri[tid] = bi;
        __syncthreads();
        #pragma unroll
        for (int off = 128; off > 0; off >>= 1) {
            if (tid < off) {
                float ov = rv[tid + off]; int oi = ri[tid + off];
                if (ov > rv[tid] || (ov == rv[tid] && oi < ri[tid])) {
                    rv[tid] = ov; ri[tid] = oi;
                }
            }
            __syncthreads();
        }
        if (tid == 0) { selv[t] = rv[0]; seli[t] = ri[0]; sv[ri[0]] = -INFINITY; }
        __syncthreads();
    }

    if (tid < KTOP) {
        const float m = selv[0];     // row max = first selection
        float e; int idx;
        if (tid < kc) { e = expf(selv[tid] - m); idx = seli[tid]; }
        else          { e = 0.0f;                idx = n + (tid - kc); }  // -inf ties: lowest index first
        float sum = e;
        #pragma unroll
        for (int off = 16; off > 0; off >>= 1)
            sum += __shfl_xor_sync(0xffffffffu, sum, off);
        const size_t base = (size_t)row * KTOP;
        out[base + tid] = (float)idx;                         // top_indices (as f32)
        out[(size_t)NROWS * KTOP + base + tid] = e / sum;     // weights
    }
}

extern "C" void kernel_launch(void* const* d_in, const int* in_sizes, int n_in,
                              void* d_out, int out_size)
{
    (void)in_sizes; (void)n_in; (void)out_size;
    const float* x   = (const float*)d_in[0];
    const float* Wi1 = (const float*)d_in[1];
    const float* bi1 = (const float*)d_in[2];
    const float* Wi2 = (const float*)d_in[3];
    const float* bi2 = (const float*)d_in[4];
    const float* Wf1 = (const float*)d_in[5];
    const float* bf1 = (const float*)d_in[6];
    const float* Wf2 = (const float*)d_in[7];
    const float* bf2 = (const float*)d_in[8];
    const float* loc = (const float*)d_in[9];
    // d_in[10..13] (Wn1,bn1,Wn2,bn2) feed an output-unused branch; d_in[14] mask is all-true.

    static float *p_Hi = nullptr, *p_Hf = nullptr, *p_int = nullptr,
                 *p_ft = nullptr, *p_sc = nullptr;
    if (!p_Hi) {
        cudaGetSymbolAddress((void**)&p_Hi,  g_Hi);
        cudaGetSymbolAddress((void**)&p_Hf,  g_Hf);
        cudaGetSymbolAddress((void**)&p_int, g_intents);
        cudaGetSymbolAddress((void**)&p_ft,  g_featT);
        cudaGetSymbolAddress((void**)&p_sc,  g_scores);
    }

    const dim3 thr(256);
    // Layer 1 (gelu): (8192x512)@(512x256)
    gemm_mlp<<<dim3(256 / BN, NROWS / BM), thr>>>(x,    Wi1, bi1, p_Hi,  256, 512, MODE_GELU);
    gemm_mlp<<<dim3(256 / BN, NROWS / BM), thr>>>(x,    Wf1, bf1, p_Hf,  256, 512, MODE_GELU);
    // Layer 2: (8192x256)@(256x512); features stored transposed per batch
    gemm_mlp<<<dim3(512 / BN, NROWS / BM), thr>>>(p_Hi, Wi2, bi2, p_int, 512, 256, MODE_BIAS);
    gemm_mlp<<<dim3(512 / BN, NROWS / BM), thr>>>(p_Hf, Wf2, bf2, p_ft,  512, 256, MODE_TRANS);
    // Scores (lower triangle tiles only) + bias + causal mask
    gemm_scores<<<dim3(SS / BN, SS / BM, BB), thr>>>(p_int, p_ft, loc, p_sc);
    // Exact top-32 + softmax per row
    topk_kernel<<<NROWS, thr>>>(p_sc, (float*)d_out);
}